// round 2
// baseline (speedup 1.0000x reference)
#include <cuda_runtime.h>
#include <cuda_bf16.h>
#include <cstdint>

// Problem constants
#define BB 8
#define NN 2048
#define CC 1024
#define HH 16
#define DD 64
#define MM (BB * NN)        // 16384 rows
#define K3 (3 * CC)         // 3072
#define KER 5

// ---------------------------------------------------------------------------
// Scratch (device globals; no allocations allowed)
// ---------------------------------------------------------------------------
__device__ float g_qkv[(size_t)MM * K3];        // 201 MB: qkv, focus applied in-place to q,k
__device__ float g_obuf[(size_t)MM * CC];       // 64 MB: attention out + dwc residual
__device__ float g_kv[BB * HH * DD * DD];       // per-head K^T V
__device__ float g_ksum[BB * HH * DD];          // per-head sum_n k
__device__ float g_part[256 * 2 * CC];          // BN partial sums [block][sum|sumsq][ch]
__device__ float g_a[CC], g_shift[CC], g_scale[CC];

// ---------------------------------------------------------------------------
// BN stats: stage 1 partial sums (deterministic, no atomics)
// grid 256 blocks x 256 threads; block handles 64 rows
// ---------------------------------------------------------------------------
__global__ void bn_partial_kernel(const float* __restrict__ x) {
    const int blk = blockIdx.x;
    const int tid = threadIdx.x;
    float s[4] = {0.f, 0.f, 0.f, 0.f};
    float ss[4] = {0.f, 0.f, 0.f, 0.f};
    const int r0 = blk * 64;
    for (int r = 0; r < 64; ++r) {
        const float* row = x + (size_t)(r0 + r) * CC;
#pragma unroll
        for (int j = 0; j < 4; ++j) {
            float v = row[tid + j * 256];
            s[j] += v;
            ss[j] += v * v;
        }
    }
#pragma unroll
    for (int j = 0; j < 4; ++j) {
        g_part[(size_t)blk * 2048 + tid + j * 256] = s[j];
        g_part[(size_t)blk * 2048 + 1024 + tid + j * 256] = ss[j];
    }
}

// ---------------------------------------------------------------------------
// BN stats stage 2: finalize per-channel a/shift, and softplus(scale_p)
// grid 4 x 256
// ---------------------------------------------------------------------------
__global__ void bn_finalize_kernel(const float* __restrict__ gamma,
                                   const float* __restrict__ beta,
                                   const float* __restrict__ scale_p) {
    const int ch = blockIdx.x * 256 + threadIdx.x;
    float s = 0.f, ss = 0.f;
    for (int b = 0; b < 256; ++b) {
        s += g_part[(size_t)b * 2048 + ch];
        ss += g_part[(size_t)b * 2048 + 1024 + ch];
    }
    const float inv = 1.0f / (float)MM;
    float mean = s * inv;
    float var = ss * inv - mean * mean;
    float rstd = rsqrtf(var + 1e-5f);
    float a = rstd * gamma[ch];
    g_a[ch] = a;
    g_shift[ch] = beta[ch] - mean * a;
    // stable softplus
    float p = scale_p[ch];
    g_scale[ch] = fmaxf(p, 0.f) + log1pf(expf(-fabsf(p)));
}

// ---------------------------------------------------------------------------
// Classic 128x128 SGEMM, BK=8, 256 threads, 8x8 per thread.
// C[m,n] = sum_k Atr(A[m,k]) * B[k,n] + bias[n]
// APPLY_BN: A element transformed as x*a[k]+shift[k] (fused BatchNorm)
// All dims assumed divisible (they are: 16384, 3072/1024, 1024).
// ---------------------------------------------------------------------------
template <bool APPLY_BN>
__global__ void __launch_bounds__(256) sgemm128x128(
    const float* __restrict__ A, const float* __restrict__ B,
    const float* __restrict__ bias, float* __restrict__ C,
    int Ndim, int Kdim)
{
    __shared__ float As[8][128];
    __shared__ float Bs[8][128];
    const int tid = threadIdx.x;
    const int row0 = blockIdx.y * 128;
    const int col0 = blockIdx.x * 128;
    const int arow = tid >> 1;
    const int acol = (tid & 1) * 4;
    const int brow = tid >> 5;
    const int bcol = (tid & 31) * 4;
    const int tx = tid & 15, ty = tid >> 4;

    const float* Ap = A + (size_t)(row0 + arow) * Kdim + acol;
    const float* Bp = B + (size_t)brow * Ndim + col0 + bcol;

    float acc[8][8];
#pragma unroll
    for (int i = 0; i < 8; ++i)
#pragma unroll
        for (int j = 0; j < 8; ++j) acc[i][j] = 0.f;

    for (int k0 = 0; k0 < Kdim; k0 += 8) {
        float4 av = *(const float4*)(Ap + k0);
        if (APPLY_BN) {
            const int c = k0 + acol;
            av.x = av.x * g_a[c + 0] + g_shift[c + 0];
            av.y = av.y * g_a[c + 1] + g_shift[c + 1];
            av.z = av.z * g_a[c + 2] + g_shift[c + 2];
            av.w = av.w * g_a[c + 3] + g_shift[c + 3];
        }
        As[acol + 0][arow] = av.x;
        As[acol + 1][arow] = av.y;
        As[acol + 2][arow] = av.z;
        As[acol + 3][arow] = av.w;
        *(float4*)&Bs[brow][bcol] = *(const float4*)(Bp + (size_t)k0 * Ndim);
        __syncthreads();
#pragma unroll
        for (int kk = 0; kk < 8; ++kk) {
            float ra[8], rb[8];
            *(float4*)&ra[0] = *(const float4*)&As[kk][ty * 8];
            *(float4*)&ra[4] = *(const float4*)&As[kk][ty * 8 + 4];
            *(float4*)&rb[0] = *(const float4*)&Bs[kk][tx * 8];
            *(float4*)&rb[4] = *(const float4*)&Bs[kk][tx * 8 + 4];
#pragma unroll
            for (int i = 0; i < 8; ++i)
#pragma unroll
                for (int j = 0; j < 8; ++j)
                    acc[i][j] = fmaf(ra[i], rb[j], acc[i][j]);
        }
        __syncthreads();
    }
#pragma unroll
    for (int i = 0; i < 8; ++i) {
        const size_t r = (size_t)(row0 + ty * 8 + i);
        float* Cr = C + r * Ndim + col0 + tx * 8;
        const float* br = bias + col0 + tx * 8;
#pragma unroll
        for (int j = 0; j < 8; ++j) Cr[j] = acc[i][j] + br[j];
    }
}

// ---------------------------------------------------------------------------
// Focus: for each row (of q and of k): t=(relu+1e-6)/scale; n1=||t||;
// u=t^3; out = u * n1/||u||. Row length C=1024, block 256, 4 elems/thread.
// In-place on g_qkv.
// ---------------------------------------------------------------------------
__device__ __forceinline__ float block_sum256(float v, float* sh) {
    const int lane = threadIdx.x & 31, w = threadIdx.x >> 5;
#pragma unroll
    for (int o = 16; o; o >>= 1) v += __shfl_xor_sync(0xffffffffu, v, o);
    if (lane == 0) sh[w] = v;
    __syncthreads();
    if (w == 0) {
        float t = (lane < 8) ? sh[lane] : 0.f;
#pragma unroll
        for (int o = 4; o; o >>= 1) t += __shfl_xor_sync(0xffffffffu, t, o);
        if (lane == 0) sh[0] = t;
    }
    __syncthreads();
    float r = sh[0];
    __syncthreads();
    return r;
}

__global__ void __launch_bounds__(256) focus_kernel() {
    __shared__ float sh[8];
    const int row = blockIdx.x;
    const int tid = threadIdx.x;
    float4 sc4 = *(const float4*)&g_scale[tid * 4];
    const float scl[4] = {sc4.x, sc4.y, sc4.z, sc4.w};

#pragma unroll
    for (int seg = 0; seg < 2; ++seg) {
        float* base = g_qkv + (size_t)row * K3 + seg * CC;
        float4 v = *(const float4*)(base + tid * 4);
        float t[4];
        t[0] = (fmaxf(v.x, 0.f) + 1e-6f) / scl[0];
        t[1] = (fmaxf(v.y, 0.f) + 1e-6f) / scl[1];
        t[2] = (fmaxf(v.z, 0.f) + 1e-6f) / scl[2];
        t[3] = (fmaxf(v.w, 0.f) + 1e-6f) / scl[3];
        float s1 = t[0] * t[0] + t[1] * t[1] + t[2] * t[2] + t[3] * t[3];
        float n1sq = block_sum256(s1, sh);
        float u[4];
        float s2 = 0.f;
#pragma unroll
        for (int i = 0; i < 4; ++i) {
            u[i] = t[i] * t[i] * t[i];
            s2 += u[i] * u[i];
        }
        float n3sq = block_sum256(s2, sh);
        float r = sqrtf(n1sq) * rsqrtf(n3sq);
        float4 o;
        o.x = u[0] * r; o.y = u[1] * r; o.z = u[2] * r; o.w = u[3] * r;
        *(float4*)(base + tid * 4) = o;
    }
}

// ---------------------------------------------------------------------------
// Per-head kv = K^T V (64x64) and ksum. grid = B*H blocks, 256 threads.
// ---------------------------------------------------------------------------
__global__ void __launch_bounds__(256) kv_kernel() {
    const int bh = blockIdx.x;
    const int b = bh >> 4, h = bh & 15;
    __shared__ float Ks[64][68];
    __shared__ float Vs[64][68];
    __shared__ float kred[4][64];
    const int tid = threadIdx.x;
    const int tr = tid >> 4, tc = tid & 15;
    const int lr = tid >> 4;          // load row base 0..15
    const int lc4 = (tid & 15) * 4;   // load col (float4)

    float acc[4][4];
#pragma unroll
    for (int i = 0; i < 4; ++i)
#pragma unroll
        for (int j = 0; j < 4; ++j) acc[i][j] = 0.f;
    float kpart = 0.f;
    const int scol = tid & 63, srg = tid >> 6;

    const size_t baseK = (size_t)(b * NN) * K3 + CC + h * DD;
    const size_t baseV = baseK + CC;

    for (int n0 = 0; n0 < NN; n0 += 64) {
#pragma unroll
        for (int i = 0; i < 4; ++i) {
            const int r = lr + i * 16;
            const size_t off = (size_t)(n0 + r) * K3 + lc4;
            *(float4*)&Ks[r][lc4] = *(const float4*)(g_qkv + baseK + off);
            *(float4*)&Vs[r][lc4] = *(const float4*)(g_qkv + baseV + off);
        }
        __syncthreads();
#pragma unroll
        for (int kk = 0; kk < 64; ++kk) {
            float ra[4], rb[4];
#pragma unroll
            for (int i = 0; i < 4; ++i) {
                ra[i] = Ks[kk][tr * 4 + i];
                rb[i] = Vs[kk][tc * 4 + i];
            }
#pragma unroll
            for (int i = 0; i < 4; ++i)
#pragma unroll
                for (int j = 0; j < 4; ++j)
                    acc[i][j] = fmaf(ra[i], rb[j], acc[i][j]);
        }
#pragma unroll
        for (int r = 0; r < 16; ++r) kpart += Ks[srg * 16 + r][scol];
        __syncthreads();
    }
    kred[srg][scol] = kpart;
    __syncthreads();
    if (tid < 64)
        g_ksum[bh * DD + tid] = kred[0][tid] + kred[1][tid] + kred[2][tid] + kred[3][tid];
#pragma unroll
    for (int i = 0; i < 4; ++i)
#pragma unroll
        for (int j = 0; j < 4; ++j)
            g_kv[(size_t)bh * 4096 + (tr * 4 + i) * 64 + tc * 4 + j] = acc[i][j];
}

// ---------------------------------------------------------------------------
// o = (q @ kv) * z ; z = 1/(q . ksum + 1e-6). Writes g_obuf in (B,N,C) layout.
// grid (N/64, B*H), 256 threads = 8 warps; warp handles 8 rows.
// ---------------------------------------------------------------------------
__global__ void __launch_bounds__(256) o_kernel() {
    const int bh = blockIdx.y;
    const int b = bh >> 4, h = bh & 15;
    const int nchunk = blockIdx.x;
    __shared__ float kvs[64][65];
    __shared__ float ks[64];
    const int tid = threadIdx.x;
    const int lane = tid & 31, warp = tid >> 5;

    for (int idx = tid; idx < 4096; idx += 256)
        kvs[idx >> 6][idx & 63] = g_kv[(size_t)bh * 4096 + idx];
    if (tid < 64) ks[tid] = g_ksum[bh * DD + tid];
    __syncthreads();

    for (int rr = 0; rr < 8; ++rr) {
        const int n = nchunk * 64 + warp * 8 + rr;
        const size_t gr = (size_t)(b * NN + n);
        const float* qrow = g_qkv + gr * K3 + h * DD;
        float qa = qrow[lane];
        float qb = qrow[lane + 32];
        float zp = qa * ks[lane] + qb * ks[lane + 32];
#pragma unroll
        for (int o = 16; o; o >>= 1) zp += __shfl_xor_sync(0xffffffffu, zp, o);
        float z = 1.0f / (zp + 1e-6f);
        float o1 = 0.f, o2 = 0.f;
#pragma unroll
        for (int d = 0; d < 32; ++d) {
            float qd = __shfl_sync(0xffffffffu, qa, d);
            o1 = fmaf(qd, kvs[d][lane], o1);
            o2 = fmaf(qd, kvs[d][lane + 32], o2);
        }
#pragma unroll
        for (int d = 0; d < 32; ++d) {
            float qd = __shfl_sync(0xffffffffu, qb, d);
            o1 = fmaf(qd, kvs[d + 32][lane], o1);
            o2 = fmaf(qd, kvs[d + 32][lane + 32], o2);
        }
        float* orow = g_obuf + gr * CC + h * DD;
        orow[lane] = o1 * z;
        orow[lane + 32] = o2 * z;
    }
}

// ---------------------------------------------------------------------------
// Depthwise conv-5 over sequence on v, added into g_obuf.
// grid (C/256, N/16, B), 256 threads.
// ---------------------------------------------------------------------------
__global__ void __launch_bounds__(256) dwc_kernel(const float* __restrict__ w,
                                                  const float* __restrict__ bias) {
    __shared__ float vs[20][256];
    const int b = blockIdx.z;
    const int n0 = blockIdx.y * 16;
    const int c = blockIdx.x * 256 + threadIdx.x;
    const int tid = threadIdx.x;

    for (int r = 0; r < 20; ++r) {
        const int n = n0 + r - 2;
        float v = 0.f;
        if (n >= 0 && n < NN)
            v = g_qkv[(size_t)(b * NN + n) * K3 + 2 * CC + c];
        vs[r][tid] = v;
    }
    __syncthreads();
    float w0 = w[c * KER + 0], w1 = w[c * KER + 1], w2 = w[c * KER + 2],
          w3 = w[c * KER + 3], w4 = w[c * KER + 4];
    const float bb = bias[c];
#pragma unroll
    for (int r = 0; r < 16; ++r) {
        float acc = bb;
        acc = fmaf(vs[r + 0][tid], w0, acc);
        acc = fmaf(vs[r + 1][tid], w1, acc);
        acc = fmaf(vs[r + 2][tid], w2, acc);
        acc = fmaf(vs[r + 3][tid], w3, acc);
        acc = fmaf(vs[r + 4][tid], w4, acc);
        g_obuf[(size_t)(b * NN + n0 + r) * CC + c] += acc;
    }
}

// ---------------------------------------------------------------------------
// Launch
// ---------------------------------------------------------------------------
extern "C" void kernel_launch(void* const* d_in, const int* in_sizes, int n_in,
                              void* d_out, int out_size) {
    const float* x       = (const float*)d_in[0];
    const float* gamma   = (const float*)d_in[1];
    const float* beta    = (const float*)d_in[2];
    const float* Wqkv    = (const float*)d_in[3];
    const float* bqkv    = (const float*)d_in[4];
    const float* scale_p = (const float*)d_in[5];
    const float* dwc_w   = (const float*)d_in[6];
    const float* dwc_b   = (const float*)d_in[7];
    const float* Wproj   = (const float*)d_in[8];
    const float* bproj   = (const float*)d_in[9];
    float* out = (float*)d_out;

    float* qkv_ptr;  cudaGetSymbolAddress((void**)&qkv_ptr, g_qkv);
    float* obuf_ptr; cudaGetSymbolAddress((void**)&obuf_ptr, g_obuf);

    // 1. BN statistics (deterministic two-stage)
    bn_partial_kernel<<<256, 256>>>(x);
    bn_finalize_kernel<<<4, 256>>>(gamma, beta, scale_p);

    // 2. QKV GEMM with BN fused into A-tile load: (16384 x 1024) @ (1024 x 3072)
    sgemm128x128<true><<<dim3(K3 / 128, MM / 128), 256>>>(x, Wqkv, bqkv, qkv_ptr, K3, CC);

    // 3. Focused feature map on q and k (in place)
    focus_kernel<<<MM, 256>>>();

    // 4. Per-head kv = K^T V and ksum
    kv_kernel<<<BB * HH, 256>>>();

    // 5. o = (q @ kv) * z  -> g_obuf (B,N,C)
    o_kernel<<<dim3(NN / 64, BB * HH), 256>>>();

    // 6. Depthwise conv residual added into g_obuf
    dwc_kernel<<<dim3(CC / 256, NN / 16, BB), 256>>>(dwc_w, dwc_b);

    // 7. Projection GEMM: (16384 x 1024) @ (1024 x 1024) -> out
    sgemm128x128<false><<<dim3(CC / 128, MM / 128), 256>>>(obuf_ptr, Wproj, bproj, out, CC, CC);
}

// round 4
// speedup vs baseline: 2.1164x; 2.1164x over previous
#include <cuda_runtime.h>
#include <cuda_bf16.h>
#include <cstdint>

// Problem constants
#define BB 8
#define NN 2048
#define CC 1024
#define HH 16
#define DD 64
#define MM (BB * NN)        // 16384 rows
#define K3 (3 * CC)         // 3072
#define KER 5

// GEMM tiling (tf32 mma.sync path)
#define BKK 32                       // K per stage (floats) = 128 B/row
#define ASTRIDE 144                  // smem row stride in bytes (36 floats, 16B aligned, conflict-free)
#define TILE_BYTES (128 * ASTRIDE)   // 18432 per operand tile
#define STAGE (2 * TILE_BYTES)       // A + B = 36864
#define GEMM_SMEM2 (2 * STAGE)       // 73728 (double buffered)

// ---------------------------------------------------------------------------
// Scratch (device globals; no allocations allowed)
// ---------------------------------------------------------------------------
__device__ float g_qkv[(size_t)MM * K3];        // qkv; focus applied in-place to q,k
__device__ float g_obuf[(size_t)MM * CC];       // attention out + dwc residual (tf32-rounded)
__device__ float g_xtf[(size_t)MM * CC];        // x pre-rounded to tf32
__device__ float g_kv[BB * HH * DD * DD];
__device__ float g_ksum[BB * HH * DD];
__device__ float g_part[256 * 2 * CC];
__device__ float g_a[CC], g_shift[CC], g_scale[CC];
__device__ float g_wtq[(size_t)K3 * CC];        // (a ⊙ W_qkv)^T (3072 x 1024), tf32-rounded
__device__ float g_wtp[(size_t)CC * CC];        // W_proj^T (1024 x 1024), tf32-rounded
__device__ float g_bias2[K3];                   // b_qkv + shift @ W_qkv

// ---------------------------------------------------------------------------
// PTX helpers
// ---------------------------------------------------------------------------
__device__ __forceinline__ uint32_t smem_u32(const void* p) {
    uint32_t a;
    asm("{ .reg .u64 t; cvta.to.shared.u64 t, %1; cvt.u32.u64 %0, t; }" : "=r"(a) : "l"(p));
    return a;
}
__device__ __forceinline__ float to_tf32(float x) {
    float r;
    asm("cvt.rna.tf32.f32 %0, %1;" : "=f"(r) : "f"(x));
    return r;
}
__device__ __forceinline__ void cp_async16(uint32_t saddr, const void* gptr) {
    asm volatile("cp.async.cg.shared.global [%0], [%1], 16;" :: "r"(saddr), "l"(gptr) : "memory");
}
__device__ __forceinline__ void cp_commit() {
    asm volatile("cp.async.commit_group;" ::: "memory");
}
template <int N>
__device__ __forceinline__ void cp_wait() {
    asm volatile("cp.async.wait_group %0;" :: "n"(N) : "memory");
}
__device__ __forceinline__ uint32_t lds32(uint32_t addr) {
    uint32_t v;
    asm volatile("ld.shared.b32 %0, [%1];" : "=r"(v) : "r"(addr));
    return v;
}
__device__ __forceinline__ void mma_tf32(float* c, const uint32_t* a, const uint32_t* b) {
    asm volatile(
        "mma.sync.aligned.m16n8k8.row.col.f32.tf32.tf32.f32 "
        "{%0,%1,%2,%3}, {%4,%5,%6,%7}, {%8,%9}, {%0,%1,%2,%3};"
        : "+f"(c[0]), "+f"(c[1]), "+f"(c[2]), "+f"(c[3])
        : "r"(a[0]), "r"(a[1]), "r"(a[2]), "r"(a[3]), "r"(b[0]), "r"(b[1]));
}

// ---------------------------------------------------------------------------
// BN stats: stage 1 partial sums (deterministic, no atomics)
// ---------------------------------------------------------------------------
__global__ void bn_partial_kernel(const float* __restrict__ x) {
    const int blk = blockIdx.x;
    const int tid = threadIdx.x;
    float s[4] = {0.f, 0.f, 0.f, 0.f};
    float ss[4] = {0.f, 0.f, 0.f, 0.f};
    const int r0 = blk * 64;
    for (int r = 0; r < 64; ++r) {
        const float* row = x + (size_t)(r0 + r) * CC;
#pragma unroll
        for (int j = 0; j < 4; ++j) {
            float v = row[tid + j * 256];
            s[j] += v;
            ss[j] += v * v;
        }
    }
#pragma unroll
    for (int j = 0; j < 4; ++j) {
        g_part[(size_t)blk * 2048 + tid + j * 256] = s[j];
        g_part[(size_t)blk * 2048 + 1024 + tid + j * 256] = ss[j];
    }
}

__global__ void bn_finalize_kernel(const float* __restrict__ gamma,
                                   const float* __restrict__ beta,
                                   const float* __restrict__ scale_p) {
    const int ch = blockIdx.x * 256 + threadIdx.x;
    float s = 0.f, ss = 0.f;
    for (int b = 0; b < 256; ++b) {
        s += g_part[(size_t)b * 2048 + ch];
        ss += g_part[(size_t)b * 2048 + 1024 + ch];
    }
    const float inv = 1.0f / (float)MM;
    float mean = s * inv;
    float var = ss * inv - mean * mean;
    float rstd = rsqrtf(var + 1e-5f);
    float a = rstd * gamma[ch];
    g_a[ch] = a;
    g_shift[ch] = beta[ch] - mean * a;
    float p = scale_p[ch];
    g_scale[ch] = fmaxf(p, 0.f) + log1pf(expf(-fabsf(p)));
}

// ---------------------------------------------------------------------------
// Elementwise tf32 RNA pre-round (x -> g_xtf). n4 float4s.
// ---------------------------------------------------------------------------
__global__ void __launch_bounds__(256) rna_kernel(const float* __restrict__ in,
                                                  float* __restrict__ out) {
    const int i = blockIdx.x * 256 + threadIdx.x;
    float4 v = ((const float4*)in)[i];
    v.x = to_tf32(v.x); v.y = to_tf32(v.y); v.z = to_tf32(v.z); v.w = to_tf32(v.w);
    ((float4*)out)[i] = v;
}

// ---------------------------------------------------------------------------
// Transpose W (K,N) -> Wt (N,K) with tf32 RNA; SCALE folds g_a[k] in (BN).
// ---------------------------------------------------------------------------
template <bool SCALE>
__global__ void __launch_bounds__(256) transpose_rna_kernel(
    const float* __restrict__ W, float* __restrict__ Wt, int K, int N)
{
    __shared__ float t[32][33];
    const int n0 = blockIdx.x * 32, k0 = blockIdx.y * 32;
    const int tx = threadIdx.x & 31, ty = threadIdx.x >> 5;
#pragma unroll
    for (int i = 0; i < 4; ++i)
        t[ty + i * 8][tx] = W[(size_t)(k0 + ty + i * 8) * N + n0 + tx];
    __syncthreads();
    const float ak = SCALE ? g_a[k0 + tx] : 1.0f;
#pragma unroll
    for (int i = 0; i < 4; ++i)
        Wt[(size_t)(n0 + ty + i * 8) * K + k0 + tx] = to_tf32(ak * t[tx][ty + i * 8]);
}

// ---------------------------------------------------------------------------
// Fold BN shift into qkv bias: bias2[n] = b[n] + sum_k shift[k] * W[k][n]
// ---------------------------------------------------------------------------
__global__ void __launch_bounds__(256) biasfold_kernel(const float* __restrict__ W,
                                                       const float* __restrict__ b) {
    const int n = blockIdx.x * 256 + threadIdx.x;
    float s = b[n];
    for (int k = 0; k < CC; ++k)
        s += g_shift[k] * W[(size_t)k * K3 + n];
    g_bias2[n] = s;
}

// ---------------------------------------------------------------------------
// tf32 mma.sync GEMM: C[m,n] = sum_k A[m,k]*Bt[n,k] + bias[n]
// Block 128x128, BK=32, 8 warps (4m x 2n), warp tile 32x64, 2-stage cp.async.
// A and Bt must be tf32 pre-rounded.
// ---------------------------------------------------------------------------
__global__ void __launch_bounds__(256) gemm_mma(
    const float* __restrict__ A, const float* __restrict__ Bt,
    const float* __restrict__ bias, float* __restrict__ C,
    int Ndim, int Kdim)
{
    extern __shared__ char sm[];
    const int tid = threadIdx.x;
    const int lane = tid & 31, w = tid >> 5;
    const int wm = w & 3, wn = w >> 2;
    const int row0 = blockIdx.y * 128, col0 = blockIdx.x * 128;
    const uint32_t sbase = smem_u32(sm);

    // cp.async loader mapping: 2 threads per 128B row, 4 x 16B each
    const int lrow = tid >> 1, lhalf = tid & 1;
    const float* gA = A + (size_t)(row0 + lrow) * Kdim + lhalf * 16;
    const float* gB = Bt + (size_t)(col0 + lrow) * Kdim + lhalf * 16;
    const uint32_t sA_off = (uint32_t)(lrow * ASTRIDE + lhalf * 64);

    float acc[2][8][4];
#pragma unroll
    for (int mi = 0; mi < 2; ++mi)
#pragma unroll
        for (int ni = 0; ni < 8; ++ni)
#pragma unroll
            for (int j = 0; j < 4; ++j) acc[mi][ni][j] = 0.f;

    const int lr = lane >> 2, lc = lane & 3;
    const uint32_t aoff0 = (uint32_t)((wm * 32 + lr) * ASTRIDE + lc * 4);
    const uint32_t boff0 = (uint32_t)((wn * 64 + lr) * ASTRIDE + lc * 4);

    const int T = Kdim / BKK;

    // prologue: stage 0
    {
        const uint32_t sa = sbase + sA_off;
        const uint32_t sb = sa + TILE_BYTES;
#pragma unroll
        for (int i = 0; i < 4; ++i) {
            cp_async16(sa + i * 16, gA + i * 4);
            cp_async16(sb + i * 16, gB + i * 4);
        }
        cp_commit();
    }

    for (int t = 0; t < T; ++t) {
        const int buf = t & 1;
        if (t + 1 < T) {
            const uint32_t sa = sbase + (buf ^ 1) * STAGE + sA_off;
            const uint32_t sb = sa + TILE_BYTES;
            const float* ga = gA + (t + 1) * BKK;
            const float* gb = gB + (t + 1) * BKK;
#pragma unroll
            for (int i = 0; i < 4; ++i) {
                cp_async16(sa + i * 16, ga + i * 4);
                cp_async16(sb + i * 16, gb + i * 4);
            }
            cp_commit();
            cp_wait<1>();
        } else {
            cp_wait<0>();
        }
        __syncthreads();

        const uint32_t abase = sbase + buf * STAGE + aoff0;
        const uint32_t bbase = sbase + buf * STAGE + TILE_BYTES + boff0;
#pragma unroll
        for (int ks = 0; ks < 4; ++ks) {
            const uint32_t ka = abase + ks * 32;   // ks*8 floats
            const uint32_t kb = bbase + ks * 32;
            uint32_t af[2][4];
            uint32_t bf[8][2];
#pragma unroll
            for (int mi = 0; mi < 2; ++mi) {
                af[mi][0] = lds32(ka + (mi * 16) * ASTRIDE);
                af[mi][1] = lds32(ka + (mi * 16 + 8) * ASTRIDE);
                af[mi][2] = lds32(ka + (mi * 16) * ASTRIDE + 16);
                af[mi][3] = lds32(ka + (mi * 16 + 8) * ASTRIDE + 16);
            }
#pragma unroll
            for (int ni = 0; ni < 8; ++ni) {
                bf[ni][0] = lds32(kb + (ni * 8) * ASTRIDE);
                bf[ni][1] = lds32(kb + (ni * 8) * ASTRIDE + 16);
            }
#pragma unroll
            for (int mi = 0; mi < 2; ++mi)
#pragma unroll
                for (int ni = 0; ni < 8; ++ni)
                    mma_tf32(acc[mi][ni], af[mi], bf[ni]);
        }
        __syncthreads();
    }

    // epilogue: c0,c1 -> row, cols 2lc,2lc+1 ; c2,c3 -> row+8
    const float* brow = bias + col0 + wn * 64;
#pragma unroll
    for (int mi = 0; mi < 2; ++mi) {
        const int mrow = row0 + wm * 32 + mi * 16 + lr;
#pragma unroll
        for (int half = 0; half < 2; ++half) {
            float* Cr = C + (size_t)(mrow + half * 8) * Ndim + col0 + wn * 64;
#pragma unroll
            for (int ni = 0; ni < 8; ++ni) {
                float2 o;
                o.x = acc[mi][ni][half * 2 + 0] + brow[ni * 8 + 2 * lc];
                o.y = acc[mi][ni][half * 2 + 1] + brow[ni * 8 + 2 * lc + 1];
                *(float2*)(Cr + ni * 8 + 2 * lc) = o;
            }
        }
    }
}

// ---------------------------------------------------------------------------
// Focus: t=(relu+1e-6)/scale; out = t^3 * ||t|| / ||t^3|| (rows of q and k)
// ---------------------------------------------------------------------------
__device__ __forceinline__ float block_sum256(float v, float* sh) {
    const int lane = threadIdx.x & 31, w = threadIdx.x >> 5;
#pragma unroll
    for (int o = 16; o; o >>= 1) v += __shfl_xor_sync(0xffffffffu, v, o);
    if (lane == 0) sh[w] = v;
    __syncthreads();
    if (w == 0) {
        float t = (lane < 8) ? sh[lane] : 0.f;
#pragma unroll
        for (int o = 4; o; o >>= 1) t += __shfl_xor_sync(0xffffffffu, t, o);
        if (lane == 0) sh[0] = t;
    }
    __syncthreads();
    float r = sh[0];
    __syncthreads();
    return r;
}

__global__ void __launch_bounds__(256) focus_kernel() {
    __shared__ float sh[8];
    const int row = blockIdx.x;
    const int tid = threadIdx.x;
    float4 sc4 = *(const float4*)&g_scale[tid * 4];
    const float scl[4] = {sc4.x, sc4.y, sc4.z, sc4.w};

#pragma unroll
    for (int seg = 0; seg < 2; ++seg) {
        float* base = g_qkv + (size_t)row * K3 + seg * CC;
        float4 vv = *(const float4*)(base + tid * 4);
        float t[4];
        t[0] = (fmaxf(vv.x, 0.f) + 1e-6f) / scl[0];
        t[1] = (fmaxf(vv.y, 0.f) + 1e-6f) / scl[1];
        t[2] = (fmaxf(vv.z, 0.f) + 1e-6f) / scl[2];
        t[3] = (fmaxf(vv.w, 0.f) + 1e-6f) / scl[3];
        float s1 = t[0] * t[0] + t[1] * t[1] + t[2] * t[2] + t[3] * t[3];
        float n1sq = block_sum256(s1, sh);
        float u[4];
        float s2 = 0.f;
#pragma unroll
        for (int i = 0; i < 4; ++i) {
            u[i] = t[i] * t[i] * t[i];
            s2 += u[i] * u[i];
        }
        float n3sq = block_sum256(s2, sh);
        float r = sqrtf(n1sq) * rsqrtf(n3sq);
        float4 o;
        o.x = u[0] * r; o.y = u[1] * r; o.z = u[2] * r; o.w = u[3] * r;
        *(float4*)(base + tid * 4) = o;
    }
}

// ---------------------------------------------------------------------------
// Per-head kv = K^T V (64x64) and ksum. grid = B*H blocks, 256 threads.
// ---------------------------------------------------------------------------
__global__ void __launch_bounds__(256) kv_kernel() {
    const int bh = blockIdx.x;
    const int b = bh >> 4, h = bh & 15;
    __shared__ float Ks[64][68];
    __shared__ float Vs[64][68];
    __shared__ float kred[4][64];
    const int tid = threadIdx.x;
    const int tr = tid >> 4, tc = tid & 15;
    const int lr = tid >> 4;
    const int lc4 = (tid & 15) * 4;

    float acc[4][4];
#pragma unroll
    for (int i = 0; i < 4; ++i)
#pragma unroll
        for (int j = 0; j < 4; ++j) acc[i][j] = 0.f;
    float kpart = 0.f;
    const int scol = tid & 63, srg = tid >> 6;

    const size_t baseK = (size_t)(b * NN) * K3 + CC + h * DD;
    const size_t baseV = baseK + CC;

    for (int n0 = 0; n0 < NN; n0 += 64) {
#pragma unroll
        for (int i = 0; i < 4; ++i) {
            const int r = lr + i * 16;
            const size_t off = (size_t)(n0 + r) * K3 + lc4;
            *(float4*)&Ks[r][lc4] = *(const float4*)(g_qkv + baseK + off);
            *(float4*)&Vs[r][lc4] = *(const float4*)(g_qkv + baseV + off);
        }
        __syncthreads();
#pragma unroll
        for (int kk = 0; kk < 64; ++kk) {
            float ra[4], rbv[4];
#pragma unroll
            for (int i = 0; i < 4; ++i) {
                ra[i] = Ks[kk][tr * 4 + i];
                rbv[i] = Vs[kk][tc * 4 + i];
            }
#pragma unroll
            for (int i = 0; i < 4; ++i)
#pragma unroll
                for (int j = 0; j < 4; ++j)
                    acc[i][j] = fmaf(ra[i], rbv[j], acc[i][j]);
        }
#pragma unroll
        for (int r = 0; r < 16; ++r) kpart += Ks[srg * 16 + r][scol];
        __syncthreads();
    }
    kred[srg][scol] = kpart;
    __syncthreads();
    if (tid < 64)
        g_ksum[bh * DD + tid] = kred[0][tid] + kred[1][tid] + kred[2][tid] + kred[3][tid];
#pragma unroll
    for (int i = 0; i < 4; ++i)
#pragma unroll
        for (int j = 0; j < 4; ++j)
            g_kv[(size_t)bh * 4096 + (tr * 4 + i) * 64 + tc * 4 + j] = acc[i][j];
}

// ---------------------------------------------------------------------------
// o = (q @ kv) * z ; z = 1/(q . ksum + 1e-6). Writes g_obuf (B,N,C).
// ---------------------------------------------------------------------------
__global__ void __launch_bounds__(256) o_kernel() {
    const int bh = blockIdx.y;
    const int b = bh >> 4, h = bh & 15;
    const int nchunk = blockIdx.x;
    __shared__ float kvs[64][65];
    __shared__ float ks[64];
    const int tid = threadIdx.x;
    const int lane = tid & 31, warp = tid >> 5;

    for (int idx = tid; idx < 4096; idx += 256)
        kvs[idx >> 6][idx & 63] = g_kv[(size_t)bh * 4096 + idx];
    if (tid < 64) ks[tid] = g_ksum[bh * DD + tid];
    __syncthreads();

    for (int rr = 0; rr < 8; ++rr) {
        const int n = nchunk * 64 + warp * 8 + rr;
        const size_t gr = (size_t)(b * NN + n);
        const float* qrow = g_qkv + gr * K3 + h * DD;
        float qa = qrow[lane];
        float qb = qrow[lane + 32];
        float zp = qa * ks[lane] + qb * ks[lane + 32];
#pragma unroll
        for (int o = 16; o; o >>= 1) zp += __shfl_xor_sync(0xffffffffu, zp, o);
        float z = 1.0f / (zp + 1e-6f);
        float o1 = 0.f, o2 = 0.f;
#pragma unroll
        for (int d = 0; d < 32; ++d) {
            float qd = __shfl_sync(0xffffffffu, qa, d);
            o1 = fmaf(qd, kvs[d][lane], o1);
            o2 = fmaf(qd, kvs[d][lane + 32], o2);
        }
#pragma unroll
        for (int d = 0; d < 32; ++d) {
            float qd = __shfl_sync(0xffffffffu, qb, d);
            o1 = fmaf(qd, kvs[d + 32][lane], o1);
            o2 = fmaf(qd, kvs[d + 32][lane + 32], o2);
        }
        float* orow = g_obuf + gr * CC + h * DD;
        orow[lane] = o1 * z;
        orow[lane + 32] = o2 * z;
    }
}

// ---------------------------------------------------------------------------
// Depthwise conv-5 over sequence on v, added into g_obuf, tf32-rounded on
// write (g_obuf feeds the tf32 proj GEMM's A operand).
// ---------------------------------------------------------------------------
__global__ void __launch_bounds__(256) dwc_kernel(const float* __restrict__ w,
                                                  const float* __restrict__ bias) {
    __shared__ float vs[20][256];
    const int b = blockIdx.z;
    const int n0 = blockIdx.y * 16;
    const int c = blockIdx.x * 256 + threadIdx.x;
    const int tid = threadIdx.x;

    for (int r = 0; r < 20; ++r) {
        const int n = n0 + r - 2;
        float v = 0.f;
        if (n >= 0 && n < NN)
            v = g_qkv[(size_t)(b * NN + n) * K3 + 2 * CC + c];
        vs[r][tid] = v;
    }
    __syncthreads();
    float w0 = w[c * KER + 0], w1 = w[c * KER + 1], w2 = w[c * KER + 2],
          w3 = w[c * KER + 3], w4 = w[c * KER + 4];
    const float bbv = bias[c];
#pragma unroll
    for (int r = 0; r < 16; ++r) {
        float acc = bbv;
        acc = fmaf(vs[r + 0][tid], w0, acc);
        acc = fmaf(vs[r + 1][tid], w1, acc);
        acc = fmaf(vs[r + 2][tid], w2, acc);
        acc = fmaf(vs[r + 3][tid], w3, acc);
        acc = fmaf(vs[r + 4][tid], w4, acc);
        const size_t idx = (size_t)(b * NN + n0 + r) * CC + c;
        g_obuf[idx] = to_tf32(g_obuf[idx] + acc);
    }
}

// ---------------------------------------------------------------------------
// Launch
// ---------------------------------------------------------------------------
extern "C" void kernel_launch(void* const* d_in, const int* in_sizes, int n_in,
                              void* d_out, int out_size) {
    const float* x       = (const float*)d_in[0];
    const float* gamma   = (const float*)d_in[1];
    const float* beta    = (const float*)d_in[2];
    const float* Wqkv    = (const float*)d_in[3];
    const float* bqkv    = (const float*)d_in[4];
    const float* scale_p = (const float*)d_in[5];
    const float* dwc_w   = (const float*)d_in[6];
    const float* dwc_b   = (const float*)d_in[7];
    const float* Wproj   = (const float*)d_in[8];
    const float* bproj   = (const float*)d_in[9];
    float* out = (float*)d_out;

    float* qkv_ptr;  cudaGetSymbolAddress((void**)&qkv_ptr, g_qkv);
    float* obuf_ptr; cudaGetSymbolAddress((void**)&obuf_ptr, g_obuf);
    float* xtf_ptr;  cudaGetSymbolAddress((void**)&xtf_ptr, g_xtf);
    float* wtq_ptr;  cudaGetSymbolAddress((void**)&wtq_ptr, g_wtq);
    float* wtp_ptr;  cudaGetSymbolAddress((void**)&wtp_ptr, g_wtp);
    float* b2_ptr;   cudaGetSymbolAddress((void**)&b2_ptr, g_bias2);

    cudaFuncSetAttribute(gemm_mma, cudaFuncAttributeMaxDynamicSharedMemorySize, GEMM_SMEM2);

    // 1. BN statistics
    bn_partial_kernel<<<256, 256>>>(x);
    bn_finalize_kernel<<<4, 256>>>(gamma, beta, scale_p);

    // 2. Prep: x tf32 pre-round; weights transposed+RNA (BN scale folded into Wqkv);
    //    BN shift folded into qkv bias.
    rna_kernel<<<(MM * CC / 4) / 256, 256>>>(x, xtf_ptr);
    transpose_rna_kernel<true><<<dim3(K3 / 32, CC / 32), 256>>>(Wqkv, wtq_ptr, CC, K3);
    transpose_rna_kernel<false><<<dim3(CC / 32, CC / 32), 256>>>(Wproj, wtp_ptr, CC, CC);
    biasfold_kernel<<<K3 / 256, 256>>>(Wqkv, bqkv);

    // 3. QKV GEMM (tf32 mma.sync)
    gemm_mma<<<dim3(K3 / 128, MM / 128), 256, GEMM_SMEM2>>>(
        xtf_ptr, wtq_ptr, b2_ptr, qkv_ptr, K3, CC);

    // 4. Focused feature map on q and k (in place)
    focus_kernel<<<MM, 256>>>();

    // 5. Per-head kv = K^T V and ksum
    kv_kernel<<<BB * HH, 256>>>();

    // 6. o = (q @ kv) * z  -> g_obuf (B,N,C)
    o_kernel<<<dim3(NN / 64, BB * HH), 256>>>();

    // 7. Depthwise conv residual added into g_obuf (tf32-rounded on write)
    dwc_kernel<<<dim3(CC / 256, NN / 16, BB), 256>>>(dwc_w, dwc_b);

    // 8. Projection GEMM (tf32 mma.sync)
    gemm_mma<<<dim3(CC / 128, MM / 128), 256, GEMM_SMEM2>>>(
        obuf_ptr, wtp_ptr, bproj, out, CC, CC);
}

// round 8
// speedup vs baseline: 3.4185x; 1.6152x over previous
#include <cuda_runtime.h>
#include <cuda_fp16.h>
#include <cstdint>

// Problem constants
#define BB 8
#define NN 2048
#define CC 1024
#define HH 16
#define DD 64
#define MM (BB * NN)        // 16384 rows
#define K3 (3 * CC)         // 3072
#define KER 5

// GEMM tiling (fp16 mma.sync m16n8k16 + ldmatrix)
#define BKH 64                        // K halves per stage = 128 B/row
#define HSTRIDE 144                   // smem row stride bytes (72 halves, conflict-free)
#define HTILE (128 * HSTRIDE)         // 18432 per operand tile
#define HSTAGE (2 * HTILE)            // A + B = 36864
#define GEMM_SMEM3 (2 * HSTAGE)       // 73728 double-buffered

#define KVSPLIT 8

// ---------------------------------------------------------------------------
// Scratch (device globals; no allocations allowed)
// ---------------------------------------------------------------------------
__device__ float  g_qkv[(size_t)MM * K3];       // qkv f32; focus in-place on q,k
__device__ float  g_obuf[(size_t)MM * CC];      // attention out (f32)
__device__ __half g_oh[(size_t)MM * CC];        // attention+dwc (half, proj A operand)
__device__ __half g_xh[(size_t)MM * CC];        // x in half
__device__ __half g_whq[(size_t)K3 * CC];       // (a ⊙ W_qkv)^T half
__device__ __half g_whp[(size_t)CC * CC];       // W_proj^T half
__device__ float  g_kv[BB * HH * DD * DD];
__device__ float  g_ksum[BB * HH * DD];
__device__ float  g_kvp[(size_t)BB * HH * KVSPLIT * DD * DD];
__device__ float  g_ksp[BB * HH * KVSPLIT * DD];
__device__ float  g_part[256 * 2 * CC];
__device__ float  g_a[CC], g_shift[CC], g_scale[CC];
__device__ float  g_bias2[K3];                  // b_qkv + shift @ W_qkv

// ---------------------------------------------------------------------------
// PTX helpers
// ---------------------------------------------------------------------------
__device__ __forceinline__ uint32_t smem_u32(const void* p) {
    uint32_t a;
    asm("{ .reg .u64 t; cvta.to.shared.u64 t, %1; cvt.u32.u64 %0, t; }" : "=r"(a) : "l"(p));
    return a;
}
__device__ __forceinline__ void cp_async16(uint32_t saddr, const void* gptr) {
    asm volatile("cp.async.cg.shared.global [%0], [%1], 16;" :: "r"(saddr), "l"(gptr) : "memory");
}
__device__ __forceinline__ void cp_commit() {
    asm volatile("cp.async.commit_group;" ::: "memory");
}
template <int N>
__device__ __forceinline__ void cp_wait() {
    asm volatile("cp.async.wait_group %0;" :: "n"(N) : "memory");
}
__device__ __forceinline__ void ldm_x4(uint32_t* r, uint32_t addr) {
    asm volatile("ldmatrix.sync.aligned.m8n8.x4.shared.b16 {%0,%1,%2,%3}, [%4];"
                 : "=r"(r[0]), "=r"(r[1]), "=r"(r[2]), "=r"(r[3]) : "r"(addr));
}
__device__ __forceinline__ void mma_f16(float* c, const uint32_t* a, const uint32_t* b) {
    asm volatile(
        "mma.sync.aligned.m16n8k16.row.col.f32.f16.f16.f32 "
        "{%0,%1,%2,%3}, {%4,%5,%6,%7}, {%8,%9}, {%0,%1,%2,%3};"
        : "+f"(c[0]), "+f"(c[1]), "+f"(c[2]), "+f"(c[3])
        : "r"(a[0]), "r"(a[1]), "r"(a[2]), "r"(a[3]), "r"(b[0]), "r"(b[1]));
}

// ---------------------------------------------------------------------------
// BN stats: stage 1 partial sums (deterministic, no atomics)
// ---------------------------------------------------------------------------
__global__ void bn_partial_kernel(const float* __restrict__ x) {
    const int blk = blockIdx.x;
    const int tid = threadIdx.x;
    float s[4] = {0.f, 0.f, 0.f, 0.f};
    float ss[4] = {0.f, 0.f, 0.f, 0.f};
    const int r0 = blk * 64;
    for (int r = 0; r < 64; ++r) {
        const float* row = x + (size_t)(r0 + r) * CC;
#pragma unroll
        for (int j = 0; j < 4; ++j) {
            float v = row[tid + j * 256];
            s[j] += v;
            ss[j] += v * v;
        }
    }
#pragma unroll
    for (int j = 0; j < 4; ++j) {
        g_part[(size_t)blk * 2048 + tid + j * 256] = s[j];
        g_part[(size_t)blk * 2048 + 1024 + tid + j * 256] = ss[j];
    }
}

__global__ void bn_finalize_kernel(const float* __restrict__ gamma,
                                   const float* __restrict__ beta,
                                   const float* __restrict__ scale_p) {
    const int ch = blockIdx.x * 256 + threadIdx.x;
    float s = 0.f, ss = 0.f;
    for (int b = 0; b < 256; ++b) {
        s += g_part[(size_t)b * 2048 + ch];
        ss += g_part[(size_t)b * 2048 + 1024 + ch];
    }
    const float inv = 1.0f / (float)MM;
    float mean = s * inv;
    float var = ss * inv - mean * mean;
    float rstd = rsqrtf(var + 1e-5f);
    float a = rstd * gamma[ch];
    g_a[ch] = a;
    g_shift[ch] = beta[ch] - mean * a;
    float p = scale_p[ch];
    g_scale[ch] = fmaxf(p, 0.f) + log1pf(expf(-fabsf(p)));
}

// ---------------------------------------------------------------------------
// x (f32) -> half
// ---------------------------------------------------------------------------
__global__ void __launch_bounds__(256) f2h_kernel(const float* __restrict__ in,
                                                  __half* __restrict__ out) {
    const int i = blockIdx.x * 256 + threadIdx.x;
    float4 v = ((const float4*)in)[i];
    __half2 h0 = __floats2half2_rn(v.x, v.y);
    __half2 h1 = __floats2half2_rn(v.z, v.w);
    ((__half2*)out)[2 * i + 0] = h0;
    ((__half2*)out)[2 * i + 1] = h1;
}

// ---------------------------------------------------------------------------
// Transpose W (K,N) -> Wt (N,K) half; SCALE folds g_a[k] (BN).
// ---------------------------------------------------------------------------
template <bool SCALE>
__global__ void __launch_bounds__(256) transpose_h_kernel(
    const float* __restrict__ W, __half* __restrict__ Wt, int K, int N)
{
    __shared__ float t[32][33];
    const int n0 = blockIdx.x * 32, k0 = blockIdx.y * 32;
    const int tx = threadIdx.x & 31, ty = threadIdx.x >> 5;
#pragma unroll
    for (int i = 0; i < 4; ++i)
        t[ty + i * 8][tx] = W[(size_t)(k0 + ty + i * 8) * N + n0 + tx];
    __syncthreads();
    const float ak = SCALE ? g_a[k0 + tx] : 1.0f;
#pragma unroll
    for (int i = 0; i < 4; ++i)
        Wt[(size_t)(n0 + ty + i * 8) * K + k0 + tx] = __float2half_rn(ak * t[tx][ty + i * 8]);
}

// ---------------------------------------------------------------------------
// Fold BN shift into qkv bias: bias2[n] = b[n] + sum_k shift[k] * W[k][n]
// ---------------------------------------------------------------------------
__global__ void __launch_bounds__(256) biasfold_kernel(const float* __restrict__ W,
                                                       const float* __restrict__ b) {
    const int n = blockIdx.x * 256 + threadIdx.x;
    float s = b[n];
    for (int k = 0; k < CC; ++k)
        s += g_shift[k] * W[(size_t)k * K3 + n];
    g_bias2[n] = s;
}

// ---------------------------------------------------------------------------
// fp16 mma.sync GEMM: C[m,n] = sum_k A[m,k]*Bt[n,k] + bias[n]  (f32 accum)
// Block 128x128, BK=64 halves, 8 warps (4m x 2n), warp 32x64, 2-stage cp.async,
// ldmatrix.x4 fragment loads.
// ---------------------------------------------------------------------------
__global__ void __launch_bounds__(256, 2) gemm_hmma(
    const __half* __restrict__ A, const __half* __restrict__ Bt,
    const float* __restrict__ bias, float* __restrict__ C,
    int Ndim, int Kdim)
{
    extern __shared__ char sm[];
    const int tid = threadIdx.x;
    const int lane = tid & 31, w = tid >> 5;
    const int wm = w & 3, wn = w >> 2;
    const int row0 = blockIdx.y * 128, col0 = blockIdx.x * 128;
    const uint32_t sbase = smem_u32(sm);

    // cp.async loader: thread t -> row t>>1, 64B half (t&1), 4 x 16B chunks
    const int lrow = tid >> 1, lh = tid & 1;
    const __half* gA = A + (size_t)(row0 + lrow) * Kdim + lh * 32;
    const __half* gB = Bt + (size_t)(col0 + lrow) * Kdim + lh * 32;
    const uint32_t sOff = (uint32_t)(lrow * HSTRIDE + lh * 64);

    float acc[2][8][4];
#pragma unroll
    for (int mi = 0; mi < 2; ++mi)
#pragma unroll
        for (int ni = 0; ni < 8; ++ni)
#pragma unroll
            for (int j = 0; j < 4; ++j) acc[mi][ni][j] = 0.f;

    // ldmatrix per-lane address components
    const uint32_t aoff0 = (uint32_t)((wm * 32 + (lane & 15)) * HSTRIDE + (lane >> 4) * 16);
    const uint32_t boff0 = (uint32_t)((wn * 64 + (lane & 7) + (lane >> 4) * 8) * HSTRIDE +
                                      ((lane >> 3) & 1) * 16);

    const int T = Kdim / BKH;

    // prologue: stage 0
    {
        const uint32_t sa = sbase + sOff;
        const uint32_t sb = sa + HTILE;
#pragma unroll
        for (int i = 0; i < 4; ++i) {
            cp_async16(sa + i * 16, gA + i * 8);
            cp_async16(sb + i * 16, gB + i * 8);
        }
        cp_commit();
    }

    for (int t = 0; t < T; ++t) {
        const int buf = t & 1;
        if (t + 1 < T) {
            const uint32_t sa = sbase + (buf ^ 1) * HSTAGE + sOff;
            const uint32_t sb = sa + HTILE;
            const __half* ga = gA + (t + 1) * BKH;
            const __half* gb = gB + (t + 1) * BKH;
#pragma unroll
            for (int i = 0; i < 4; ++i) {
                cp_async16(sa + i * 16, ga + i * 8);
                cp_async16(sb + i * 16, gb + i * 8);
            }
            cp_commit();
            cp_wait<1>();
        } else {
            cp_wait<0>();
        }
        __syncthreads();

        const uint32_t abase = sbase + buf * HSTAGE + aoff0;
        const uint32_t bbase = sbase + buf * HSTAGE + HTILE + boff0;
#pragma unroll
        for (int ks = 0; ks < 4; ++ks) {
            uint32_t af[2][4];
            uint32_t bf[4][4];
#pragma unroll
            for (int mi = 0; mi < 2; ++mi)
                ldm_x4(af[mi], abase + mi * 16 * HSTRIDE + ks * 32);
#pragma unroll
            for (int nt = 0; nt < 4; ++nt)
                ldm_x4(bf[nt], bbase + nt * 16 * HSTRIDE + ks * 32);
#pragma unroll
            for (int mi = 0; mi < 2; ++mi)
#pragma unroll
                for (int ni = 0; ni < 8; ++ni)
                    mma_f16(acc[mi][ni], af[mi], &bf[ni >> 1][(ni & 1) * 2]);
        }
        __syncthreads();
    }

    // epilogue
    const int lr = lane >> 2, lc = lane & 3;
    const float* brow = bias + col0 + wn * 64;
#pragma unroll
    for (int mi = 0; mi < 2; ++mi) {
        const int mrow = row0 + wm * 32 + mi * 16 + lr;
#pragma unroll
        for (int half = 0; half < 2; ++half) {
            float* Cr = C + (size_t)(mrow + half * 8) * Ndim + col0 + wn * 64;
#pragma unroll
            for (int ni = 0; ni < 8; ++ni) {
                float2 o;
                o.x = acc[mi][ni][half * 2 + 0] + brow[ni * 8 + 2 * lc];
                o.y = acc[mi][ni][half * 2 + 1] + brow[ni * 8 + 2 * lc + 1];
                *(float2*)(Cr + ni * 8 + 2 * lc) = o;
            }
        }
    }
}

// ---------------------------------------------------------------------------
// Focus: t=(relu+1e-6)/scale; out = t^3 * ||t|| / ||t^3|| (rows of q and k)
// ---------------------------------------------------------------------------
__device__ __forceinline__ float block_sum256(float v, float* sh) {
    const int lane = threadIdx.x & 31, w = threadIdx.x >> 5;
#pragma unroll
    for (int o = 16; o; o >>= 1) v += __shfl_xor_sync(0xffffffffu, v, o);
    if (lane == 0) sh[w] = v;
    __syncthreads();
    if (w == 0) {
        float t = (lane < 8) ? sh[lane] : 0.f;
#pragma unroll
        for (int o = 4; o; o >>= 1) t += __shfl_xor_sync(0xffffffffu, t, o);
        if (lane == 0) sh[0] = t;
    }
    __syncthreads();
    float r = sh[0];
    __syncthreads();
    return r;
}

__global__ void __launch_bounds__(256) focus_kernel() {
    __shared__ float sh[8];
    const int row = blockIdx.x;
    const int tid = threadIdx.x;
    float4 sc4 = *(const float4*)&g_scale[tid * 4];
    const float scl[4] = {sc4.x, sc4.y, sc4.z, sc4.w};

#pragma unroll
    for (int seg = 0; seg < 2; ++seg) {
        float* base = g_qkv + (size_t)row * K3 + seg * CC;
        float4 vv = *(const float4*)(base + tid * 4);
        float t[4];
        t[0] = (fmaxf(vv.x, 0.f) + 1e-6f) / scl[0];
        t[1] = (fmaxf(vv.y, 0.f) + 1e-6f) / scl[1];
        t[2] = (fmaxf(vv.z, 0.f) + 1e-6f) / scl[2];
        t[3] = (fmaxf(vv.w, 0.f) + 1e-6f) / scl[3];
        float s1 = t[0] * t[0] + t[1] * t[1] + t[2] * t[2] + t[3] * t[3];
        float n1sq = block_sum256(s1, sh);
        float u[4];
        float s2 = 0.f;
#pragma unroll
        for (int i = 0; i < 4; ++i) {
            u[i] = t[i] * t[i] * t[i];
            s2 += u[i] * u[i];
        }
        float n3sq = block_sum256(s2, sh);
        float r = sqrtf(n1sq) * rsqrtf(n3sq);
        float4 o;
        o.x = u[0] * r; o.y = u[1] * r; o.z = u[2] * r; o.w = u[3] * r;
        *(float4*)(base + tid * 4) = o;
    }
}

// ---------------------------------------------------------------------------
// Per-head partial kv = K^T V and ksum over a slice of N. grid (B*H, KVSPLIT).
// ---------------------------------------------------------------------------
__global__ void __launch_bounds__(256) kv_part_kernel() {
    const int bh = blockIdx.x;
    const int chunk = blockIdx.y;
    const int b = bh >> 4, h = bh & 15;
    __shared__ float Ks[64][68];
    __shared__ float Vs[64][68];
    __shared__ float kred[4][64];
    const int tid = threadIdx.x;
    const int tr = tid >> 4, tc = tid & 15;
    const int lr = tid >> 4;
    const int lc4 = (tid & 15) * 4;

    float acc[4][4];
#pragma unroll
    for (int i = 0; i < 4; ++i)
#pragma unroll
        for (int j = 0; j < 4; ++j) acc[i][j] = 0.f;
    float kpart = 0.f;
    const int scol = tid & 63, srg = tid >> 6;

    const size_t baseK = (size_t)(b * NN) * K3 + CC + h * DD;
    const size_t baseV = baseK + CC;
    const int nlo = chunk * (NN / KVSPLIT);
    const int nhi = nlo + (NN / KVSPLIT);

    for (int n0 = nlo; n0 < nhi; n0 += 64) {
#pragma unroll
        for (int i = 0; i < 4; ++i) {
            const int r = lr + i * 16;
            const size_t off = (size_t)(n0 + r) * K3 + lc4;
            *(float4*)&Ks[r][lc4] = *(const float4*)(g_qkv + baseK + off);
            *(float4*)&Vs[r][lc4] = *(const float4*)(g_qkv + baseV + off);
        }
        __syncthreads();
#pragma unroll
        for (int kk = 0; kk < 64; ++kk) {
            float ra[4], rbv[4];
#pragma unroll
            for (int i = 0; i < 4; ++i) {
                ra[i] = Ks[kk][tr * 4 + i];
                rbv[i] = Vs[kk][tc * 4 + i];
            }
#pragma unroll
            for (int i = 0; i < 4; ++i)
#pragma unroll
                for (int j = 0; j < 4; ++j)
                    acc[i][j] = fmaf(ra[i], rbv[j], acc[i][j]);
        }
#pragma unroll
        for (int r = 0; r < 16; ++r) kpart += Ks[srg * 16 + r][scol];
        __syncthreads();
    }
    kred[srg][scol] = kpart;
    __syncthreads();
    const size_t pb = (size_t)(bh * KVSPLIT + chunk);
    if (tid < 64)
        g_ksp[pb * DD + tid] = kred[0][tid] + kred[1][tid] + kred[2][tid] + kred[3][tid];
#pragma unroll
    for (int i = 0; i < 4; ++i)
#pragma unroll
        for (int j = 0; j < 4; ++j)
            g_kvp[pb * 4096 + (tr * 4 + i) * 64 + tc * 4 + j] = acc[i][j];
}

__global__ void __launch_bounds__(256) kv_reduce_kernel() {
    const int bh = blockIdx.x;
    const int tid = threadIdx.x;
    for (int idx = tid; idx < 4096; idx += 256) {
        float s = 0.f;
#pragma unroll
        for (int c = 0; c < KVSPLIT; ++c)
            s += g_kvp[(size_t)(bh * KVSPLIT + c) * 4096 + idx];
        g_kv[(size_t)bh * 4096 + idx] = s;
    }
    if (tid < 64) {
        float s = 0.f;
#pragma unroll
        for (int c = 0; c < KVSPLIT; ++c)
            s += g_ksp[(size_t)(bh * KVSPLIT + c) * DD + tid];
        g_ksum[bh * DD + tid] = s;
    }
}

// ---------------------------------------------------------------------------
// o = (q @ kv) * z ; z = 1/(q . ksum + 1e-6). Writes g_obuf (B,N,C).
// ---------------------------------------------------------------------------
__global__ void __launch_bounds__(256) o_kernel() {
    const int bh = blockIdx.y;
    const int b = bh >> 4, h = bh & 15;
    const int nchunk = blockIdx.x;
    __shared__ float kvs[64][65];
    __shared__ float ks[64];
    const int tid = threadIdx.x;
    const int lane = tid & 31, warp = tid >> 5;

    for (int idx = tid; idx < 4096; idx += 256)
        kvs[idx >> 6][idx & 63] = g_kv[(size_t)bh * 4096 + idx];
    if (tid < 64) ks[tid] = g_ksum[bh * DD + tid];
    __syncthreads();

    for (int rr = 0; rr < 8; ++rr) {
        const int n = nchunk * 64 + warp * 8 + rr;
        const size_t gr = (size_t)(b * NN + n);
        const float* qrow = g_qkv + gr * K3 + h * DD;
        float qa = qrow[lane];
        float qb = qrow[lane + 32];
        float zp = qa * ks[lane] + qb * ks[lane + 32];
#pragma unroll
        for (int o = 16; o; o >>= 1) zp += __shfl_xor_sync(0xffffffffu, zp, o);
        float z = 1.0f / (zp + 1e-6f);
        float o1 = 0.f, o2 = 0.f;
#pragma unroll
        for (int d = 0; d < 32; ++d) {
            float qd = __shfl_sync(0xffffffffu, qa, d);
            o1 = fmaf(qd, kvs[d][lane], o1);
            o2 = fmaf(qd, kvs[d][lane + 32], o2);
        }
#pragma unroll
        for (int d = 0; d < 32; ++d) {
            float qd = __shfl_sync(0xffffffffu, qb, d);
            o1 = fmaf(qd, kvs[d + 32][lane], o1);
            o2 = fmaf(qd, kvs[d + 32][lane + 32], o2);
        }
        float* orow = g_obuf + gr * CC + h * DD;
        orow[lane] = o1 * z;
        orow[lane + 32] = o2 * z;
    }
}

// ---------------------------------------------------------------------------
// Depthwise conv-5 over sequence on v; adds o_kernel result; writes half
// (proj GEMM A operand).
// ---------------------------------------------------------------------------
__global__ void __launch_bounds__(256) dwc_kernel(const float* __restrict__ w,
                                                  const float* __restrict__ bias) {
    __shared__ float vs[20][256];
    const int b = blockIdx.z;
    const int n0 = blockIdx.y * 16;
    const int c = blockIdx.x * 256 + threadIdx.x;
    const int tid = threadIdx.x;

    for (int r = 0; r < 20; ++r) {
        const int n = n0 + r - 2;
        float v = 0.f;
        if (n >= 0 && n < NN)
            v = g_qkv[(size_t)(b * NN + n) * K3 + 2 * CC + c];
        vs[r][tid] = v;
    }
    __syncthreads();
    float w0 = w[c * KER + 0], w1 = w[c * KER + 1], w2 = w[c * KER + 2],
          w3 = w[c * KER + 3], w4 = w[c * KER + 4];
    const float bbv = bias[c];
#pragma unroll
    for (int r = 0; r < 16; ++r) {
        float acc = bbv;
        acc = fmaf(vs[r + 0][tid], w0, acc);
        acc = fmaf(vs[r + 1][tid], w1, acc);
        acc = fmaf(vs[r + 2][tid], w2, acc);
        acc = fmaf(vs[r + 3][tid], w3, acc);
        acc = fmaf(vs[r + 4][tid], w4, acc);
        const size_t idx = (size_t)(b * NN + n0 + r) * CC + c;
        g_oh[idx] = __float2half_rn(g_obuf[idx] + acc);
    }
}

// ---------------------------------------------------------------------------
// Launch
// ---------------------------------------------------------------------------
extern "C" void kernel_launch(void* const* d_in, const int* in_sizes, int n_in,
                              void* d_out, int out_size) {
    const float* x       = (const float*)d_in[0];
    const float* gamma   = (const float*)d_in[1];
    const float* beta    = (const float*)d_in[2];
    const float* Wqkv    = (const float*)d_in[3];
    const float* bqkv    = (const float*)d_in[4];
    const float* scale_p = (const float*)d_in[5];
    const float* dwc_w   = (const float*)d_in[6];
    const float* dwc_b   = (const float*)d_in[7];
    const float* Wproj   = (const float*)d_in[8];
    const float* bproj   = (const float*)d_in[9];
    float* out = (float*)d_out;

    float*  qkv_ptr; cudaGetSymbolAddress((void**)&qkv_ptr, g_qkv);
    __half* xh_ptr;  cudaGetSymbolAddress((void**)&xh_ptr, g_xh);
    __half* whq_ptr; cudaGetSymbolAddress((void**)&whq_ptr, g_whq);
    __half* whp_ptr; cudaGetSymbolAddress((void**)&whp_ptr, g_whp);
    __half* oh_ptr;  cudaGetSymbolAddress((void**)&oh_ptr, g_oh);
    float*  b2_ptr;  cudaGetSymbolAddress((void**)&b2_ptr, g_bias2);

    cudaFuncSetAttribute(gemm_hmma, cudaFuncAttributeMaxDynamicSharedMemorySize, GEMM_SMEM3);

    // 1. BN statistics
    bn_partial_kernel<<<256, 256>>>(x);
    bn_finalize_kernel<<<4, 256>>>(gamma, beta, scale_p);

    // 2. Prep: x -> half; weights -> transposed half (BN scale folded into Wqkv);
    //    BN shift folded into qkv bias.
    f2h_kernel<<<(MM * CC / 4) / 256, 256>>>(x, xh_ptr);
    transpose_h_kernel<true><<<dim3(K3 / 32, CC / 32), 256>>>(Wqkv, whq_ptr, CC, K3);
    transpose_h_kernel<false><<<dim3(CC / 32, CC / 32), 256>>>(Wproj, whp_ptr, CC, CC);
    biasfold_kernel<<<K3 / 256, 256>>>(Wqkv, bqkv);

    // 3. QKV GEMM (fp16 mma.sync, f32 accum)
    gemm_hmma<<<dim3(K3 / 128, MM / 128), 256, GEMM_SMEM3>>>(
        xh_ptr, whq_ptr, b2_ptr, qkv_ptr, K3, CC);

    // 4. Focused feature map on q and k (in place)
    focus_kernel<<<MM, 256>>>();

    // 5. Per-head kv = K^T V and ksum (split over N for occupancy, then reduce)
    kv_part_kernel<<<dim3(BB * HH, KVSPLIT), 256>>>();
    kv_reduce_kernel<<<BB * HH, 256>>>();

    // 6. o = (q @ kv) * z  -> g_obuf (B,N,C)
    o_kernel<<<dim3(NN / 64, BB * HH), 256>>>();

    // 7. Depthwise conv residual + half conversion -> g_oh
    dwc_kernel<<<dim3(CC / 256, NN / 16, BB), 256>>>(dwc_w, dwc_b);

    // 8. Projection GEMM (fp16 mma.sync)
    gemm_hmma<<<dim3(CC / 128, MM / 128), 256, GEMM_SMEM3>>>(
        oh_ptr, whp_ptr, bproj, out, CC, CC);
}

// round 9
// speedup vs baseline: 3.6955x; 1.0810x over previous
#include <cuda_runtime.h>
#include <cuda_fp16.h>
#include <cstdint>

// Problem constants
#define BB 8
#define NN 2048
#define CC 1024
#define HH 16
#define DD 64
#define MM (BB * NN)        // 16384 rows
#define K3 (3 * CC)         // 3072
#define KER 5
#define QK2 (2 * CC)        // 2048 (q|k f32 row width)

// GEMM tiling (fp16 mma.sync m16n8k16 + ldmatrix, 3-stage cp.async)
#define BKH 64                        // K halves per stage = 128 B/row
#define HSTRIDE 144                   // smem row stride bytes (72 halves, conflict-free)
#define HTILE (128 * HSTRIDE)         // 18432 per operand tile
#define HSTAGE (2 * HTILE)            // A + B = 36864
#define NSTG 3
#define GEMM_SMEM3 (NSTG * HSTAGE)    // 110592

#define KVSPLIT 8

// ---------------------------------------------------------------------------
// Scratch (device globals; no allocations allowed)
// ---------------------------------------------------------------------------
__device__ float  g_qk[(size_t)MM * QK2];       // q|k f32 (pre-focus), row width 2048
__device__ __half g_vh[(size_t)MM * CC];        // v half
__device__ __half g_qh[(size_t)MM * CC];        // q half (post-focus)
__device__ __half g_kh[(size_t)MM * CC];        // k half (post-focus)
__device__ __half g_oh[(size_t)MM * CC];        // attention+dwc (half, proj A operand)
__device__ __half g_xh[(size_t)MM * CC];        // x in half
__device__ __half g_whq[(size_t)K3 * CC];       // (a ⊙ W_qkv)^T half
__device__ __half g_whp[(size_t)CC * CC];       // W_proj^T half
__device__ float  g_kv[BB * HH * DD * DD];
__device__ float  g_ksum[BB * HH * DD];
__device__ float  g_kvp[(size_t)BB * HH * KVSPLIT * DD * DD];
__device__ float  g_ksp[BB * HH * KVSPLIT * DD];
__device__ float  g_part[256 * 2 * CC];
__device__ float  g_a[CC], g_shift[CC], g_scale[CC];
__device__ float  g_bias2[K3];                  // b_qkv + shift @ W_qkv

// ---------------------------------------------------------------------------
// PTX helpers
// ---------------------------------------------------------------------------
__device__ __forceinline__ uint32_t smem_u32(const void* p) {
    uint32_t a;
    asm("{ .reg .u64 t; cvta.to.shared.u64 t, %1; cvt.u32.u64 %0, t; }" : "=r"(a) : "l"(p));
    return a;
}
__device__ __forceinline__ void cp_async16(uint32_t saddr, const void* gptr) {
    asm volatile("cp.async.cg.shared.global [%0], [%1], 16;" :: "r"(saddr), "l"(gptr) : "memory");
}
__device__ __forceinline__ void cp_commit() {
    asm volatile("cp.async.commit_group;" ::: "memory");
}
template <int N>
__device__ __forceinline__ void cp_wait() {
    asm volatile("cp.async.wait_group %0;" :: "n"(N) : "memory");
}
__device__ __forceinline__ void ldm_x4(uint32_t* r, uint32_t addr) {
    asm volatile("ldmatrix.sync.aligned.m8n8.x4.shared.b16 {%0,%1,%2,%3}, [%4];"
                 : "=r"(r[0]), "=r"(r[1]), "=r"(r[2]), "=r"(r[3]) : "r"(addr));
}
__device__ __forceinline__ void mma_f16(float* c, const uint32_t* a, const uint32_t* b) {
    asm volatile(
        "mma.sync.aligned.m16n8k16.row.col.f32.f16.f16.f32 "
        "{%0,%1,%2,%3}, {%4,%5,%6,%7}, {%8,%9}, {%0,%1,%2,%3};"
        : "+f"(c[0]), "+f"(c[1]), "+f"(c[2]), "+f"(c[3])
        : "r"(a[0]), "r"(a[1]), "r"(a[2]), "r"(a[3]), "r"(b[0]), "r"(b[1]));
}

// ---------------------------------------------------------------------------
// BN stats partial sums fused with x -> half conversion.
// grid 256 x 256; block handles 64 rows; thread handles 4 consecutive channels.
// ---------------------------------------------------------------------------
__global__ void __launch_bounds__(256) bnf2h_kernel(const float* __restrict__ x,
                                                    __half* __restrict__ xh) {
    const int blk = blockIdx.x;
    const int tid = threadIdx.x;
    const int r0 = blk * 64;
    float s[4] = {0.f, 0.f, 0.f, 0.f};
    float ss[4] = {0.f, 0.f, 0.f, 0.f};
    for (int r = 0; r < 64; ++r) {
        const size_t rowo = (size_t)(r0 + r) * CC;
        float4 v = *(const float4*)(x + rowo + tid * 4);
        s[0] += v.x; ss[0] += v.x * v.x;
        s[1] += v.y; ss[1] += v.y * v.y;
        s[2] += v.z; ss[2] += v.z * v.z;
        s[3] += v.w; ss[3] += v.w * v.w;
        __half2 h0 = __floats2half2_rn(v.x, v.y);
        __half2 h1 = __floats2half2_rn(v.z, v.w);
        uint2 u;
        u.x = *(uint32_t*)&h0; u.y = *(uint32_t*)&h1;
        *(uint2*)(xh + rowo + tid * 4) = u;
    }
#pragma unroll
    for (int j = 0; j < 4; ++j) {
        g_part[(size_t)blk * 2048 + tid * 4 + j] = s[j];
        g_part[(size_t)blk * 2048 + 1024 + tid * 4 + j] = ss[j];
    }
}

__global__ void bn_finalize_kernel(const float* __restrict__ gamma,
                                   const float* __restrict__ beta,
                                   const float* __restrict__ scale_p) {
    const int ch = blockIdx.x * 256 + threadIdx.x;
    float s = 0.f, ss = 0.f;
    for (int b = 0; b < 256; ++b) {
        s += g_part[(size_t)b * 2048 + ch];
        ss += g_part[(size_t)b * 2048 + 1024 + ch];
    }
    const float inv = 1.0f / (float)MM;
    float mean = s * inv;
    float var = ss * inv - mean * mean;
    float rstd = rsqrtf(var + 1e-5f);
    float a = rstd * gamma[ch];
    g_a[ch] = a;
    g_shift[ch] = beta[ch] - mean * a;
    float p = scale_p[ch];
    g_scale[ch] = fmaxf(p, 0.f) + log1pf(expf(-fabsf(p)));
}

// ---------------------------------------------------------------------------
// Transpose W (K,N) -> Wt (N,K) half; SCALE folds g_a[k] (BN).
// ---------------------------------------------------------------------------
template <bool SCALE>
__global__ void __launch_bounds__(256) transpose_h_kernel(
    const float* __restrict__ W, __half* __restrict__ Wt, int K, int N)
{
    __shared__ float t[32][33];
    const int n0 = blockIdx.x * 32, k0 = blockIdx.y * 32;
    const int tx = threadIdx.x & 31, ty = threadIdx.x >> 5;
#pragma unroll
    for (int i = 0; i < 4; ++i)
        t[ty + i * 8][tx] = W[(size_t)(k0 + ty + i * 8) * N + n0 + tx];
    __syncthreads();
    const float ak = SCALE ? g_a[k0 + tx] : 1.0f;
#pragma unroll
    for (int i = 0; i < 4; ++i)
        Wt[(size_t)(n0 + ty + i * 8) * K + k0 + tx] = __float2half_rn(ak * t[tx][ty + i * 8]);
}

// ---------------------------------------------------------------------------
// Fold BN shift into qkv bias: bias2[n] = b[n] + sum_k shift[k] * W[k][n]
// ---------------------------------------------------------------------------
__global__ void __launch_bounds__(256) biasfold_kernel(const float* __restrict__ W,
                                                       const float* __restrict__ b) {
    const int n = blockIdx.x * 256 + threadIdx.x;
    float s = b[n];
    for (int k = 0; k < CC; ++k)
        s += g_shift[k] * W[(size_t)k * K3 + n];
    g_bias2[n] = s;
}

// ---------------------------------------------------------------------------
// fp16 mma.sync GEMM: C[m,n] = sum_k A[m,k]*Bt[n,k] + bias[n]  (f32 accum)
// Block 128x128, BK=64 halves, 8 warps (4m x 2n), warp 32x64, 3-stage cp.async.
// SPLIT: cols < 2048 -> f32 to Cf (stride strideF); cols >= 2048 -> half to Ch
// (stride CC). Otherwise f32 to Cf.
// ---------------------------------------------------------------------------
template <bool SPLIT>
__global__ void __launch_bounds__(256, 2) gemm_hmma(
    const __half* __restrict__ A, const __half* __restrict__ Bt,
    const float* __restrict__ bias, float* __restrict__ Cf, int strideF,
    __half* __restrict__ Ch, int Ndim, int Kdim)
{
    extern __shared__ char sm[];
    const int tid = threadIdx.x;
    const int lane = tid & 31, w = tid >> 5;
    const int wm = w & 3, wn = w >> 2;
    const int row0 = blockIdx.y * 128, col0 = blockIdx.x * 128;
    const uint32_t sbase = smem_u32(sm);

    // cp.async loader: thread t -> row t>>1, 64B half (t&1), 4 x 16B chunks
    const int lrow = tid >> 1, lh = tid & 1;
    const __half* gA = A + (size_t)(row0 + lrow) * Kdim + lh * 32;
    const __half* gB = Bt + (size_t)(col0 + lrow) * Kdim + lh * 32;
    const uint32_t sOff = (uint32_t)(lrow * HSTRIDE + lh * 64);

    float acc[2][8][4];
#pragma unroll
    for (int mi = 0; mi < 2; ++mi)
#pragma unroll
        for (int ni = 0; ni < 8; ++ni)
#pragma unroll
            for (int j = 0; j < 4; ++j) acc[mi][ni][j] = 0.f;

    const uint32_t aoff0 = (uint32_t)((wm * 32 + (lane & 15)) * HSTRIDE + (lane >> 4) * 16);
    const uint32_t boff0 = (uint32_t)((wn * 64 + (lane & 7) + (lane >> 4) * 8) * HSTRIDE +
                                      ((lane >> 3) & 1) * 16);

    const int T = Kdim / BKH;

    // prologue: stages 0, 1
#pragma unroll
    for (int s = 0; s < 2; ++s) {
        const uint32_t sa = sbase + s * HSTAGE + sOff;
        const uint32_t sb = sa + HTILE;
        const __half* ga = gA + s * BKH;
        const __half* gb = gB + s * BKH;
#pragma unroll
        for (int i = 0; i < 4; ++i) {
            cp_async16(sa + i * 16, ga + i * 8);
            cp_async16(sb + i * 16, gb + i * 8);
        }
        cp_commit();
    }

    for (int t = 0; t < T; ++t) {
        if (t == T - 1) cp_wait<0>(); else cp_wait<1>();
        __syncthreads();
        if (t + 2 < T) {
            const int sidx = (t + 2) % NSTG;
            const uint32_t sa = sbase + sidx * HSTAGE + sOff;
            const uint32_t sb = sa + HTILE;
            const __half* ga = gA + (t + 2) * BKH;
            const __half* gb = gB + (t + 2) * BKH;
#pragma unroll
            for (int i = 0; i < 4; ++i) {
                cp_async16(sa + i * 16, ga + i * 8);
                cp_async16(sb + i * 16, gb + i * 8);
            }
            cp_commit();
        }
        const int buf = t % NSTG;
        const uint32_t abase = sbase + buf * HSTAGE + aoff0;
        const uint32_t bbase = sbase + buf * HSTAGE + HTILE + boff0;
#pragma unroll
        for (int ks = 0; ks < 4; ++ks) {
            uint32_t af[2][4];
            uint32_t bf[4][4];
#pragma unroll
            for (int mi = 0; mi < 2; ++mi)
                ldm_x4(af[mi], abase + mi * 16 * HSTRIDE + ks * 32);
#pragma unroll
            for (int nt = 0; nt < 4; ++nt)
                ldm_x4(bf[nt], bbase + nt * 16 * HSTRIDE + ks * 32);
#pragma unroll
            for (int mi = 0; mi < 2; ++mi)
#pragma unroll
                for (int ni = 0; ni < 8; ++ni)
                    mma_f16(acc[mi][ni], af[mi], &bf[ni >> 1][(ni & 1) * 2]);
        }
    }
    __syncthreads();

    // epilogue
    const int lr = lane >> 2, lc = lane & 3;
    const float* brow = bias + col0 + wn * 64;
    const bool vmode = SPLIT && (col0 >= QK2);
#pragma unroll
    for (int mi = 0; mi < 2; ++mi) {
        const int mrow = row0 + wm * 32 + mi * 16 + lr;
#pragma unroll
        for (int hf = 0; hf < 2; ++hf) {
            const int r = mrow + hf * 8;
            if (!vmode) {
                float* Cr = Cf + (size_t)r * strideF + col0 + wn * 64;
#pragma unroll
                for (int ni = 0; ni < 8; ++ni) {
                    float2 o;
                    o.x = acc[mi][ni][hf * 2 + 0] + brow[ni * 8 + 2 * lc];
                    o.y = acc[mi][ni][hf * 2 + 1] + brow[ni * 8 + 2 * lc + 1];
                    *(float2*)(Cr + ni * 8 + 2 * lc) = o;
                }
            } else {
                __half* Hr = Ch + (size_t)r * CC + (col0 - QK2) + wn * 64;
#pragma unroll
                for (int ni = 0; ni < 8; ++ni) {
                    float ox = acc[mi][ni][hf * 2 + 0] + brow[ni * 8 + 2 * lc];
                    float oy = acc[mi][ni][hf * 2 + 1] + brow[ni * 8 + 2 * lc + 1];
                    *(__half2*)(Hr + ni * 8 + 2 * lc) = __floats2half2_rn(ox, oy);
                }
            }
        }
    }
}

// ---------------------------------------------------------------------------
// Focus: t=(relu+1e-6)/scale; out = t^3 * ||t|| / ||t^3||; q,k f32 -> half
// ---------------------------------------------------------------------------
__device__ __forceinline__ float block_sum256(float v, float* sh) {
    const int lane = threadIdx.x & 31, w = threadIdx.x >> 5;
#pragma unroll
    for (int o = 16; o; o >>= 1) v += __shfl_xor_sync(0xffffffffu, v, o);
    if (lane == 0) sh[w] = v;
    __syncthreads();
    if (w == 0) {
        float t = (lane < 8) ? sh[lane] : 0.f;
#pragma unroll
        for (int o = 4; o; o >>= 1) t += __shfl_xor_sync(0xffffffffu, t, o);
        if (lane == 0) sh[0] = t;
    }
    __syncthreads();
    float r = sh[0];
    __syncthreads();
    return r;
}

__global__ void __launch_bounds__(256) focus_kernel() {
    __shared__ float sh[8];
    const int row = blockIdx.x;
    const int tid = threadIdx.x;
    float4 sc4 = *(const float4*)&g_scale[tid * 4];
    const float scl[4] = {sc4.x, sc4.y, sc4.z, sc4.w};

#pragma unroll
    for (int seg = 0; seg < 2; ++seg) {
        const float* base = g_qk + (size_t)row * QK2 + seg * CC;
        __half* outp = (seg == 0 ? g_qh : g_kh) + (size_t)row * CC;
        float4 vv = *(const float4*)(base + tid * 4);
        float t[4];
        t[0] = (fmaxf(vv.x, 0.f) + 1e-6f) / scl[0];
        t[1] = (fmaxf(vv.y, 0.f) + 1e-6f) / scl[1];
        t[2] = (fmaxf(vv.z, 0.f) + 1e-6f) / scl[2];
        t[3] = (fmaxf(vv.w, 0.f) + 1e-6f) / scl[3];
        float s1 = t[0] * t[0] + t[1] * t[1] + t[2] * t[2] + t[3] * t[3];
        float n1sq = block_sum256(s1, sh);
        float u[4];
        float s2 = 0.f;
#pragma unroll
        for (int i = 0; i < 4; ++i) {
            u[i] = t[i] * t[i] * t[i];
            s2 += u[i] * u[i];
        }
        float n3sq = block_sum256(s2, sh);
        float r = sqrtf(n1sq) * rsqrtf(n3sq);
        __half2 h0 = __floats2half2_rn(u[0] * r, u[1] * r);
        __half2 h1 = __floats2half2_rn(u[2] * r, u[3] * r);
        uint2 uo;
        uo.x = *(uint32_t*)&h0; uo.y = *(uint32_t*)&h1;
        *(uint2*)(outp + tid * 4) = uo;
    }
}

// ---------------------------------------------------------------------------
// Per-head partial kv = K^T V and ksum over a slice of N. grid (B*H, KVSPLIT).
// Reads half k, v.
// ---------------------------------------------------------------------------
__global__ void __launch_bounds__(256) kv_part_kernel() {
    const int bh = blockIdx.x;
    const int chunk = blockIdx.y;
    const int b = bh >> 4, h = bh & 15;
    __shared__ float Ks[64][68];
    __shared__ float Vs[64][68];
    __shared__ float kred[4][64];
    const int tid = threadIdx.x;
    const int tr = tid >> 4, tc = tid & 15;
    const int lr = tid >> 4;
    const int lc4 = (tid & 15) * 4;

    float acc[4][4];
#pragma unroll
    for (int i = 0; i < 4; ++i)
#pragma unroll
        for (int j = 0; j < 4; ++j) acc[i][j] = 0.f;
    float kpart = 0.f;
    const int scol = tid & 63, srg = tid >> 6;

    const int nlo = chunk * (NN / KVSPLIT);
    const int nhi = nlo + (NN / KVSPLIT);

    for (int n0 = nlo; n0 < nhi; n0 += 64) {
#pragma unroll
        for (int i = 0; i < 4; ++i) {
            const int r = lr + i * 16;
            const size_t off = (size_t)(b * NN + n0 + r) * CC + h * DD + lc4;
            uint2 uk = *(const uint2*)(g_kh + off);
            uint2 uv = *(const uint2*)(g_vh + off);
            float2 k01 = __half22float2(*(__half2*)&uk.x);
            float2 k23 = __half22float2(*(__half2*)&uk.y);
            float2 v01 = __half22float2(*(__half2*)&uv.x);
            float2 v23 = __half22float2(*(__half2*)&uv.y);
            Ks[r][lc4 + 0] = k01.x; Ks[r][lc4 + 1] = k01.y;
            Ks[r][lc4 + 2] = k23.x; Ks[r][lc4 + 3] = k23.y;
            Vs[r][lc4 + 0] = v01.x; Vs[r][lc4 + 1] = v01.y;
            Vs[r][lc4 + 2] = v23.x; Vs[r][lc4 + 3] = v23.y;
        }
        __syncthreads();
#pragma unroll
        for (int kk = 0; kk < 64; ++kk) {
            float ra[4], rbv[4];
#pragma unroll
            for (int i = 0; i < 4; ++i) {
                ra[i] = Ks[kk][tr * 4 + i];
                rbv[i] = Vs[kk][tc * 4 + i];
            }
#pragma unroll
            for (int i = 0; i < 4; ++i)
#pragma unroll
                for (int j = 0; j < 4; ++j)
                    acc[i][j] = fmaf(ra[i], rbv[j], acc[i][j]);
        }
#pragma unroll
        for (int r = 0; r < 16; ++r) kpart += Ks[srg * 16 + r][scol];
        __syncthreads();
    }
    kred[srg][scol] = kpart;
    __syncthreads();
    const size_t pb = (size_t)(bh * KVSPLIT + chunk);
    if (tid < 64)
        g_ksp[pb * DD + tid] = kred[0][tid] + kred[1][tid] + kred[2][tid] + kred[3][tid];
#pragma unroll
    for (int i = 0; i < 4; ++i)
#pragma unroll
        for (int j = 0; j < 4; ++j)
            g_kvp[pb * 4096 + (tr * 4 + i) * 64 + tc * 4 + j] = acc[i][j];
}

__global__ void __launch_bounds__(256) kv_reduce_kernel() {
    const int bh = blockIdx.x;
    const int tid = threadIdx.x;
    for (int idx = tid; idx < 4096; idx += 256) {
        float s = 0.f;
#pragma unroll
        for (int c = 0; c < KVSPLIT; ++c)
            s += g_kvp[(size_t)(bh * KVSPLIT + c) * 4096 + idx];
        g_kv[(size_t)bh * 4096 + idx] = s;
    }
    if (tid < 64) {
        float s = 0.f;
#pragma unroll
        for (int c = 0; c < KVSPLIT; ++c)
            s += g_ksp[(size_t)(bh * KVSPLIT + c) * DD + tid];
        g_ksum[bh * DD + tid] = s;
    }
}

// ---------------------------------------------------------------------------
// Fused: o = (q @ kv) * z + depthwise-conv5(v) + dwc bias; writes half g_oh.
// grid (NN/64, B*H), 256 threads = 8 warps; warp handles 8 seq rows.
// ---------------------------------------------------------------------------
__global__ void __launch_bounds__(256) o_dwc_kernel(const float* __restrict__ w,
                                                    const float* __restrict__ bias) {
    const int bh = blockIdx.y;
    const int b = bh >> 4, h = bh & 15;
    const int n0 = blockIdx.x * 64;
    __shared__ float kvs[64][65];
    __shared__ float ks[64];
    __shared__ uint4 vsl4[68][8];   // v slice [n0-2, n0+66) x 64 ch (half)
    const int tid = threadIdx.x;
    const int lane = tid & 31, warp = tid >> 5;

    for (int idx = tid; idx < 4096; idx += 256)
        kvs[idx >> 6][idx & 63] = g_kv[(size_t)bh * 4096 + idx];
    if (tid < 64) ks[tid] = g_ksum[bh * DD + tid];
    for (int idx = tid; idx < 68 * 8; idx += 256) {
        const int row = idx >> 3, seg = idx & 7;
        const int n = n0 - 2 + row;
        uint4 val = make_uint4(0u, 0u, 0u, 0u);
        if (n >= 0 && n < NN)
            val = *(const uint4*)(g_vh + (size_t)(b * NN + n) * CC + h * DD + seg * 8);
        vsl4[row][seg] = val;
    }
    __syncthreads();
    const __half* vs = (const __half*)vsl4;   // [68][64]

    // per-thread conv weights for channels d=lane and d=lane+32
    const int c1 = h * DD + lane, c2 = c1 + 32;
    float w1[5], w2[5];
#pragma unroll
    for (int j = 0; j < 5; ++j) { w1[j] = w[c1 * KER + j]; w2[j] = w[c2 * KER + j]; }
    const float b1 = bias[c1], b2 = bias[c2];

    for (int rr = 0; rr < 8; ++rr) {
        const int li = warp * 8 + rr;
        const int n = n0 + li;
        const size_t gr = (size_t)(b * NN + n);
        const __half* qrow = g_qh + gr * CC + h * DD;
        float qa = __half2float(qrow[lane]);
        float qb = __half2float(qrow[lane + 32]);
        float zp = qa * ks[lane] + qb * ks[lane + 32];
#pragma unroll
        for (int o = 16; o; o >>= 1) zp += __shfl_xor_sync(0xffffffffu, zp, o);
        float z = 1.0f / (zp + 1e-6f);
        float o1 = 0.f, o2 = 0.f;
#pragma unroll
        for (int d = 0; d < 32; ++d) {
            float qd = __shfl_sync(0xffffffffu, qa, d);
            o1 = fmaf(qd, kvs[d][lane], o1);
            o2 = fmaf(qd, kvs[d][lane + 32], o2);
        }
#pragma unroll
        for (int d = 0; d < 32; ++d) {
            float qd = __shfl_sync(0xffffffffu, qb, d);
            o1 = fmaf(qd, kvs[d + 32][lane], o1);
            o2 = fmaf(qd, kvs[d + 32][lane + 32], o2);
        }
        float d1 = b1, d2 = b2;
#pragma unroll
        for (int j = 0; j < 5; ++j) {
            d1 = fmaf(w1[j], __half2float(vs[(li + j) * 64 + lane]), d1);
            d2 = fmaf(w2[j], __half2float(vs[(li + j) * 64 + lane + 32]), d2);
        }
        __half* orow = g_oh + gr * CC + h * DD;
        orow[lane] = __float2half_rn(fmaf(o1, z, d1));
        orow[lane + 32] = __float2half_rn(fmaf(o2, z, d2));
    }
}

// ---------------------------------------------------------------------------
// Launch
// ---------------------------------------------------------------------------
extern "C" void kernel_launch(void* const* d_in, const int* in_sizes, int n_in,
                              void* d_out, int out_size) {
    const float* x       = (const float*)d_in[0];
    const float* gamma   = (const float*)d_in[1];
    const float* beta    = (const float*)d_in[2];
    const float* Wqkv    = (const float*)d_in[3];
    const float* bqkv    = (const float*)d_in[4];
    const float* scale_p = (const float*)d_in[5];
    const float* dwc_w   = (const float*)d_in[6];
    const float* dwc_b   = (const float*)d_in[7];
    const float* Wproj   = (const float*)d_in[8];
    const float* bproj   = (const float*)d_in[9];
    float* out = (float*)d_out;

    float*  qk_ptr;  cudaGetSymbolAddress((void**)&qk_ptr, g_qk);
    __half* vh_ptr;  cudaGetSymbolAddress((void**)&vh_ptr, g_vh);
    __half* xh_ptr;  cudaGetSymbolAddress((void**)&xh_ptr, g_xh);
    __half* whq_ptr; cudaGetSymbolAddress((void**)&whq_ptr, g_whq);
    __half* whp_ptr; cudaGetSymbolAddress((void**)&whp_ptr, g_whp);
    __half* oh_ptr;  cudaGetSymbolAddress((void**)&oh_ptr, g_oh);
    float*  b2_ptr;  cudaGetSymbolAddress((void**)&b2_ptr, g_bias2);

    cudaFuncSetAttribute(gemm_hmma<true>,  cudaFuncAttributeMaxDynamicSharedMemorySize, GEMM_SMEM3);
    cudaFuncSetAttribute(gemm_hmma<false>, cudaFuncAttributeMaxDynamicSharedMemorySize, GEMM_SMEM3);

    // 1. BN statistics (fused with x -> half)
    bnf2h_kernel<<<256, 256>>>(x, xh_ptr);
    bn_finalize_kernel<<<4, 256>>>(gamma, beta, scale_p);

    // 2. Weights -> transposed half (BN scale folded into Wqkv); shift -> bias.
    transpose_h_kernel<true><<<dim3(K3 / 32, CC / 32), 256>>>(Wqkv, whq_ptr, CC, K3);
    transpose_h_kernel<false><<<dim3(CC / 32, CC / 32), 256>>>(Wproj, whp_ptr, CC, CC);
    biasfold_kernel<<<K3 / 256, 256>>>(Wqkv, bqkv);

    // 3. QKV GEMM: q,k -> f32 g_qk; v -> half g_vh (split epilogue)
    gemm_hmma<true><<<dim3(K3 / 128, MM / 128), 256, GEMM_SMEM3>>>(
        xh_ptr, whq_ptr, b2_ptr, qk_ptr, QK2, vh_ptr, K3, CC);

    // 4. Focused feature map: q,k f32 -> half g_qh/g_kh
    focus_kernel<<<MM, 256>>>();

    // 5. Per-head kv = K^T V and ksum (split over N, then reduce)
    kv_part_kernel<<<dim3(BB * HH, KVSPLIT), 256>>>();
    kv_reduce_kernel<<<BB * HH, 256>>>();

    // 6. Fused attention output + depthwise conv -> half g_oh
    o_dwc_kernel<<<dim3(NN / 64, BB * HH), 256>>>(dwc_w, dwc_b);

    // 7. Projection GEMM (f32 out)
    gemm_hmma<false><<<dim3(CC / 128, MM / 128), 256, GEMM_SMEM3>>>(
        oh_ptr, whp_ptr, bproj, out, CC, (__half*)nullptr, CC, CC);
}